// round 11
// baseline (speedup 1.0000x reference)
#include <cuda_runtime.h>

// PCEN: x[B=16, T=8192, N=128]
//   m_t = sigma*x_t + (1-sigma)*m_{t-1}   (EMA over T, m_{-1}=0)
//   out = (x * (m+0.1)^(-alpha) + delta)^rho - delta^rho
//
// Chunked parallel scan: |1-sigma| ~= 0.0588 -> 8-step redundant warmup.
//
// R10->R11: prefetch fixed the latency bind (issue 57->66, new best 23.1us
// kernel). Now cut issue count/element: float4 layout (LDG.128/STG.128 per
// 4 channels), scaled-EMA m~=m/sigma (update = 1 fma, m+eps = 1 fma),
// CHUNK=32 for occ~43%, PF=8 rotating prefetch kept from R10.

#define PB 16
#define PT 8192
#define PN 128
#define CHUNK 32
#define WARM 8
#define PF 8                              // prefetch depth / group size
#define NGROUP (CHUNK / PF)               // 4
#define NCHUNKS (PT / CHUNK)              // 256
#define NTASKS  (PB * NCHUNKS)            // 4096 warp-tasks (1 per row)
#define WPB 4                              // warps per block
#define NBLOCKS (NTASKS / WPB)             // 1024
#define STRIDE (PN / 4)                    // row stride in float4s = 32

// MUFU EX2 / LG2 (what __powf uses internally)
__device__ __forceinline__ float fex2(float a) {
    float r; asm("ex2.approx.f32 %0, %1;" : "=f"(r) : "f"(a)); return r;
}
__device__ __forceinline__ float flg2(float a) {
    float r; asm("lg2.approx.f32 %0, %1;" : "=f"(r) : "f"(a)); return r;
}

__global__ __launch_bounds__(32 * WPB, 7)
void pcen_kernel(const float4* __restrict__ x4,
                 const float* __restrict__ log_alpha,
                 const float* __restrict__ log_delta,
                 const float* __restrict__ log_rho,
                 const float* __restrict__ log_sigma,
                 float4* __restrict__ out4)
{
    const int lane = threadIdx.x & 31;
    const int task = blockIdx.x * WPB + (threadIdx.x >> 5);
    const int b     = task / NCHUNKS;
    const int chunk = task % NCHUNKS;

    const float sigma = expf(log_sigma[0]);
    const float om    = 1.0f - sigma;

    // per-lane params for 4 channels (accurate expf, once per thread)
    const int c = lane * 4;
    const float na0 = -expf(log_alpha[c+0]), na1 = -expf(log_alpha[c+1]);
    const float na2 = -expf(log_alpha[c+2]), na3 = -expf(log_alpha[c+3]);
    const float d0 = expf(log_delta[c+0]), d1 = expf(log_delta[c+1]);
    const float d2 = expf(log_delta[c+2]), d3 = expf(log_delta[c+3]);
    const float r0 = expf(log_rho[c+0]), r1 = expf(log_rho[c+1]);
    const float r2 = expf(log_rho[c+2]), r3 = expf(log_rho[c+3]);
    const float dr0 = powf(d0, r0), dr1 = powf(d1, r1);
    const float dr2 = powf(d2, r2), dr3 = powf(d3, r3);

    const int t0 = chunk * CHUNK;

    // scaled EMA state: ms = m/sigma;  ms_t = x_t + om*ms_{t-1}
    // m + eps materializes as fmaf(sigma, ms, eps)
    float ms0 = 0.f, ms1 = 0.f, ms2 = 0.f, ms3 = 0.f;

    const float4* xp;
    if (chunk != 0) {
        // warmup: batch all 8 loads (MLP=8), then serial EMA
        xp = x4 + ((size_t)b * PT + (t0 - WARM)) * STRIDE + lane;
        float4 wbuf[WARM];
        #pragma unroll
        for (int j = 0; j < WARM; ++j) wbuf[j] = __ldg(xp + j * STRIDE);
        #pragma unroll
        for (int j = 0; j < WARM; ++j) {
            ms0 = fmaf(om, ms0, wbuf[j].x);
            ms1 = fmaf(om, ms1, wbuf[j].y);
            ms2 = fmaf(om, ms2, wbuf[j].z);
            ms3 = fmaf(om, ms3, wbuf[j].w);
        }
        xp += WARM * STRIDE;
    } else {
        xp = x4 + ((size_t)b * PT) * STRIDE + lane;
    }

    float4* op = out4 + ((size_t)b * PT + t0) * STRIDE + lane;

    // pointwise PCEN for one timestep (updates ms*, returns output)
    auto compute = [&](float4 xv) -> float4 {
        ms0 = fmaf(om, ms0, xv.x);
        ms1 = fmaf(om, ms1, xv.y);
        ms2 = fmaf(om, ms2, xv.z);
        ms3 = fmaf(om, ms3, xv.w);
        const float e0 = fmaf(sigma, ms0, 0.1f);   // m + eps >= 0.1
        const float e1 = fmaf(sigma, ms1, 0.1f);
        const float e2 = fmaf(sigma, ms2, 0.1f);
        const float e3 = fmaf(sigma, ms3, 0.1f);
        // (m+eps)^(-alpha) = ex2(-alpha*lg2(m+eps))
        const float i0 = fex2(na0 * flg2(e0));
        const float i1 = fex2(na1 * flg2(e1));
        const float i2 = fex2(na2 * flg2(e2));
        const float i3 = fex2(na3 * flg2(e3));
        // base >= delta ~= 2, well-conditioned
        const float b0 = fmaf(xv.x, i0, d0);
        const float b1 = fmaf(xv.y, i1, d1);
        const float b2 = fmaf(xv.z, i2, d2);
        const float b3 = fmaf(xv.w, i3, d3);
        float4 o;
        o.x = fex2(r0 * flg2(b0)) - dr0;
        o.y = fex2(r1 * flg2(b1)) - dr1;
        o.z = fex2(r2 * flg2(b2)) - dr2;
        o.w = fex2(r3 * flg2(b3)) - dr3;
        return o;
    };

    // software pipeline: depth-PF rotating register buffer
    float4 buf[PF];
    #pragma unroll
    for (int j = 0; j < PF; ++j) buf[j] = __ldg(xp + j * STRIDE);
    xp += PF * STRIDE;

    #pragma unroll 1
    for (int g = 0; g < NGROUP - 1; ++g) {
        #pragma unroll
        for (int j = 0; j < PF; ++j) {
            const float4 xv = buf[j];
            buf[j] = __ldg(xp + j * STRIDE);   // prefetch next group
            op[j * STRIDE] = compute(xv);
        }
        xp += PF * STRIDE;
        op += PF * STRIDE;
    }
    // final group (no prefetch)
    #pragma unroll
    for (int j = 0; j < PF; ++j) {
        op[j * STRIDE] = compute(buf[j]);
    }
}

extern "C" void kernel_launch(void* const* d_in, const int* in_sizes, int n_in,
                              void* d_out, int out_size)
{
    const float4* x         = (const float4*)d_in[0];
    const float* log_alpha  = (const float*)d_in[1];
    const float* log_delta  = (const float*)d_in[2];
    const float* log_rho    = (const float*)d_in[3];
    const float* log_sigma  = (const float*)d_in[4];
    float4*      out        = (float4*)d_out;

    pcen_kernel<<<NBLOCKS, 32 * WPB>>>(x, log_alpha, log_delta, log_rho,
                                       log_sigma, out);
}

// round 12
// speedup vs baseline: 1.1380x; 1.1380x over previous
#include <cuda_runtime.h>

// PCEN: x[B=16, T=8192, N=128]
//   m_t = sigma*x_t + (1-sigma)*m_{t-1}   (EMA over T, m_{-1}=0)
//   out = (x * (m+0.1)^(-alpha) + delta)^rho - delta^rho
//
// Chunked parallel scan: |1-sigma| ~= 0.0588 -> 8-step redundant warmup.
//
// R11->R12: R11's float4 PF=8 buffer spilled (regs 72@cap, L1 33->43%) --
// reverted to the R10 skeleton (float2, CHUNK=64, PF=8 rotating prefetch,
// 23.1us, ~88% of the 4-MUFU/el roofline at the observed clock). This round
// halves the MUFU floor: both ex2 ops move to the FMA pipe as packed f32x2
// deg-4 Taylor polys (R8/R9-validated, rel_err 3.5e-5), leaving 2 lg2/el
// on MUFU. Scaled-EMA (ms=m/sigma) saves 2 more instrs/el.

#define PB 16
#define PT 8192
#define PN 128
#define CHUNK 64
#define WARM 8
#define PF 8                              // prefetch depth / group size
#define NGROUP (CHUNK / PF)               // 8
#define NCHUNKS (PT / CHUNK)              // 128
#define NTASKS  (PB * NCHUNKS * 2)        // 4096 warp-tasks (2 per row)
#define WPB 4                              // warps per block
#define NBLOCKS (NTASKS / WPB)             // 1024
#define STRIDE (PN / 2)                    // row stride in float2s = 64

typedef unsigned long long u64;

__device__ __forceinline__ float flg2(float a) {
    float r; asm("lg2.approx.f32 %0, %1;" : "=f"(r) : "f"(a)); return r;
}
// f32x2 packed helpers (Blackwell FFMA2 path)
__device__ __forceinline__ u64 pk2(float lo, float hi) {
    u64 r; asm("mov.b64 %0, {%1, %2};" : "=l"(r) : "f"(lo), "f"(hi)); return r;
}
__device__ __forceinline__ void upk2(float& lo, float& hi, u64 v) {
    asm("mov.b64 {%0, %1}, %2;" : "=f"(lo), "=f"(hi) : "l"(v));
}
__device__ __forceinline__ u64 fma2_(u64 a, u64 b, u64 c) {
    u64 r; asm("fma.rn.f32x2 %0, %1, %2, %3;" : "=l"(r) : "l"(a), "l"(b), "l"(c)); return r;
}
__device__ __forceinline__ u64 add2_(u64 a, u64 b) {
    u64 r; asm("add.rn.f32x2 %0, %1, %2;" : "=l"(r) : "l"(a), "l"(b)); return r;
}
__device__ __forceinline__ u64 mul2_(u64 a, u64 b) {
    u64 r; asm("mul.rn.f32x2 %0, %1, %2;" : "=l"(r) : "l"(a), "l"(b)); return r;
}

__global__ __launch_bounds__(32 * WPB, 8)
void pcen_kernel(const float2* __restrict__ x2,
                 const float* __restrict__ log_alpha,
                 const float* __restrict__ log_delta,
                 const float* __restrict__ log_rho,
                 const float* __restrict__ log_sigma,
                 float2* __restrict__ out2)
{
    const int lane = threadIdx.x & 31;
    const int task = blockIdx.x * WPB + (threadIdx.x >> 5);
    const int half = task & 1;               // which 64-channel half of the row
    const int rt   = task >> 1;              // row task
    const int b     = rt / NCHUNKS;
    const int chunk = rt % NCHUNKS;

    const float sigma = expf(log_sigma[0]);
    const float om    = 1.0f - sigma;

    // per-lane params for 2 channels (accurate expf, once per thread)
    const int c = half * 64 + lane * 2;
    const float a0 = expf(log_alpha[c+0]), a1 = expf(log_alpha[c+1]);
    const float d0 = expf(log_delta[c+0]), d1 = expf(log_delta[c+1]);
    const float r0 = expf(log_rho[c+0]),  r1 = expf(log_rho[c+1]);
    const u64 NA  = pk2(-a0, -a1);
    const u64 D2  = pk2(d0, d1);
    const u64 R2  = pk2(r0, r1);
    const u64 NDR = pk2(-powf(d0, r0), -powf(d1, r1));

    // packed constants
    const u64 OM2  = pk2(om, om);
    const u64 SGE2 = pk2(sigma, sigma);                // for m = sigma*ms
    const u64 EPS2 = pk2(0.1f, 0.1f);
    const u64 MG2  = pk2(12582912.0f, 12582912.0f);    // 1.5*2^23
    const u64 NM2  = pk2(-12582912.0f, -12582912.0f);
    const u64 N12  = pk2(-1.0f, -1.0f);
    const u64 C42  = pk2(0.00961813f, 0.00961813f);    // ln2^4/24
    const u64 C32  = pk2(0.05550411f, 0.05550411f);    // ln2^3/6
    const u64 C22  = pk2(0.24022651f, 0.24022651f);    // ln2^2/2
    const u64 C12  = pk2(0.69314718f, 0.69314718f);    // ln2
    const u64 ONE2 = pk2(1.0f, 1.0f);

    // packed exp2: magic-add round + deg-4 Taylor on [-0.5,0.5] (FMA pipe),
    // integer part inserted into exponent bits (ALU). err ~4e-5 rel.
    auto EX2P = [&](u64 y) -> u64 {
        const u64 t = add2_(y, MG2);
        float t0, t1; upk2(t0, t1, t);
        const int k0 = __float_as_int(t0) << 23;
        const int k1 = __float_as_int(t1) << 23;
        const u64 kf = add2_(t, NM2);
        const u64 g  = fma2_(kf, N12, y);        // y - round(y)
        u64 p = fma2_(g, C42, C32);
        p = fma2_(g, p, C22);
        p = fma2_(g, p, C12);
        p = fma2_(g, p, ONE2);
        float p0, p1; upk2(p0, p1, p);
        return pk2(__int_as_float(__float_as_int(p0) + k0),
                   __int_as_float(__float_as_int(p1) + k1));
    };

    const int t0 = chunk * CHUNK;
    const int coff = half * 32 + lane;       // float2 index within row

    // scaled EMA state: ms = m/sigma;  ms_t = x_t + om*ms_{t-1}
    u64 ms = pk2(0.f, 0.f);

    const float2* xp;
    if (chunk != 0) {
        // warmup: batch all 8 loads (MLP=8), then serial EMA
        xp = x2 + ((size_t)b * PT + (t0 - WARM)) * STRIDE + coff;
        float2 wbuf[WARM];
        #pragma unroll
        for (int j = 0; j < WARM; ++j) wbuf[j] = __ldg(xp + j * STRIDE);
        #pragma unroll
        for (int j = 0; j < WARM; ++j)
            ms = fma2_(OM2, ms, pk2(wbuf[j].x, wbuf[j].y));
        xp += WARM * STRIDE;
    } else {
        xp = x2 + ((size_t)b * PT) * STRIDE + coff;
    }

    float2* op = out2 + ((size_t)b * PT + t0) * STRIDE + coff;

    // pointwise PCEN for one timestep (updates ms, returns output)
    auto compute = [&](float2 xvf) -> float2 {
        const u64 xk = pk2(xvf.x, xvf.y);
        ms = fma2_(OM2, ms, xk);
        // m + eps = sigma*ms + eps >= 0.1
        const u64 me = fma2_(SGE2, ms, EPS2);
        float e0, e1; upk2(e0, e1, me);
        const u64 L = pk2(flg2(e0), flg2(e1));          // MUFU x2
        // base = x * exp2(-alpha*L) + delta >= ~2
        const u64 base = fma2_(xk, EX2P(mul2_(NA, L)), D2);
        float c0, c1; upk2(c0, c1, base);
        const u64 Lb = pk2(flg2(c0), flg2(c1));          // MUFU x2
        // out = exp2(rho*Lb) - delta^rho
        const u64 o = add2_(EX2P(mul2_(R2, Lb)), NDR);
        float o0, o1; upk2(o0, o1, o);
        return make_float2(o0, o1);
    };

    // software pipeline: depth-PF rotating register buffer
    float2 buf[PF];
    #pragma unroll
    for (int j = 0; j < PF; ++j) buf[j] = __ldg(xp + j * STRIDE);
    xp += PF * STRIDE;

    #pragma unroll 1
    for (int g = 0; g < NGROUP - 1; ++g) {
        #pragma unroll
        for (int j = 0; j < PF; ++j) {
            const float2 xv = buf[j];
            buf[j] = __ldg(xp + j * STRIDE);   // prefetch next group
            op[j * STRIDE] = compute(xv);
        }
        xp += PF * STRIDE;
        op += PF * STRIDE;
    }
    // final group (no prefetch)
    #pragma unroll
    for (int j = 0; j < PF; ++j) {
        op[j * STRIDE] = compute(buf[j]);
    }
}

extern "C" void kernel_launch(void* const* d_in, const int* in_sizes, int n_in,
                              void* d_out, int out_size)
{
    const float2* x         = (const float2*)d_in[0];
    const float* log_alpha  = (const float*)d_in[1];
    const float* log_delta  = (const float*)d_in[2];
    const float* log_rho    = (const float*)d_in[3];
    const float* log_sigma  = (const float*)d_in[4];
    float2*      out        = (float2*)d_out;

    pcen_kernel<<<NBLOCKS, 32 * WPB>>>(x, log_alpha, log_delta, log_rho,
                                       log_sigma, out);
}